// round 15
// baseline (speedup 1.0000x reference)
#include <cuda_runtime.h>
#include <math.h>

#define NB 8
#define Qn 300
#define CCn 92
#define CFn 2048
#define HFn 42
#define Mn 20
#define TOPKn 5
#define NCLS 91
#define HW 1333
#define PIX (HFn*HFn)       /* 1764 */
#define NEGV (-1e11f)
#define NCH 64              /* channel chunks, 32 channels each */
#define FPAD 43             /* padded row stride (conflict-free) */
#define MBLK 38             /* means blocks per image */
#define RBLK (NCH*NB)       /* 512 streaming blocks */
#define IBLK 128            /* init blocks: 128*448=57344 >= 56028 */
#define TBLK 176            /* table blocks: 176*14=2464 >= 2400 */
#define FGRID (RBLK + IBLK + TBLK)   /* 816 */

__device__ float g_Fpart[NCH][NB*PIX];
__device__ float g_F[NB][PIX];
__device__ float g_A[HW+1][HFn];     /* cumulative bilinear weights */
__device__ float g_means[NB][Qn];
/* per-query tables, computed concurrently with the DRAM-bound reduce */
__device__ float g_lm[NB][Qn];
__device__ float g_inv[NB][Qn];
__device__ float g_lse2[NB][Qn];
__device__ float g_ce90[NB][Qn];
__device__ float g_bceobj[NB][Qn];
__device__ float g_rest[NB][Qn];
__device__ float g_partial[NB];
__device__ unsigned int g_done_r[NB];   /* zero-init; self-resetting */
__device__ unsigned int g_done_m[NB];   /* zero-init; self-resetting */
__device__ unsigned int g_ctr;          /* zero-init; self-resetting */

/* ---------------- helpers ---------------- */
__device__ __forceinline__ float sigmoid_stable(float x) {
    if (x >= 0.f) return 1.f / (1.f + expf(-x));
    float e = expf(x);
    return e / (1.f + e);
}

__device__ __forceinline__ float rest_term(float x) {
    float sg = sigmoid_stable(x);
    return -fmaxf(log1pf(-sg), -100.f);
}

/* warp-collective softmax stats over one 91-class row */
__device__ __forceinline__ void row_softmax(const float* __restrict__ lg,
                                            int lane, float& lm, float& se, float& se2) {
    lm = -3.4e38f;
    for (int c = lane; c < NCLS; c += 32) lm = fmaxf(lm, lg[c]);
#pragma unroll
    for (int off = 16; off > 0; off >>= 1)
        lm = fmaxf(lm, __shfl_xor_sync(0xFFFFFFFFu, lm, off));
    se = 0.f;
    for (int c = lane; c < NCLS; c += 32) se += expf(lg[c] - lm);
#pragma unroll
    for (int off = 16; off > 0; off >>= 1)
        se += __shfl_xor_sync(0xFFFFFFFFu, se, off);
    float inv = 1.f / se, pmax = inv;
    se2 = 0.f;
    for (int c = lane; c < NCLS; c += 32)
        se2 += expf(expf(lg[c] - lm) * inv - pmax);
#pragma unroll
    for (int off = 16; off > 0; off >>= 1)
        se2 += __shfl_xor_sync(0xFFFFFFFFu, se2, off);
}

/* -- kernel 1: [0,512) stream reduce (+fused F sum) | [512,640) weight init |
      [640,816) softmax tables.  1D grid: streamers dispatch first. -- */
__global__ void __launch_bounds__(448, 3) k_front(const float* __restrict__ img,
                                                  const float* __restrict__ logits) {
    int bid = blockIdx.x;
    int t = threadIdx.x;
    if (bid < RBLK) {
        int chunk = bid >> 3;              /* 0..63, 32 channels each */
        int b = bid & 7;
        if (t < PIX / 4) {
            const float4* base = (const float4*)img + ((size_t)b * CFn + (size_t)chunk * 32) * (PIX / 4) + t;
            float ax = 0.f, ay = 0.f, az = 0.f, aw = 0.f;
#pragma unroll
            for (int c = 0; c < 32; c += 8) {
                float4 v0 = base[(size_t)(c + 0) * (PIX / 4)];
                float4 v1 = base[(size_t)(c + 1) * (PIX / 4)];
                float4 v2 = base[(size_t)(c + 2) * (PIX / 4)];
                float4 v3 = base[(size_t)(c + 3) * (PIX / 4)];
                float4 v4 = base[(size_t)(c + 4) * (PIX / 4)];
                float4 v5 = base[(size_t)(c + 5) * (PIX / 4)];
                float4 v6 = base[(size_t)(c + 6) * (PIX / 4)];
                float4 v7 = base[(size_t)(c + 7) * (PIX / 4)];
                ax += v0.x; ay += v0.y; az += v0.z; aw += v0.w;
                ax += v1.x; ay += v1.y; az += v1.z; aw += v1.w;
                ax += v2.x; ay += v2.y; az += v2.z; aw += v2.w;
                ax += v3.x; ay += v3.y; az += v3.z; aw += v3.w;
                ax += v4.x; ay += v4.y; az += v4.z; aw += v4.w;
                ax += v5.x; ay += v5.y; az += v5.z; aw += v5.w;
                ax += v6.x; ay += v6.y; az += v6.z; aw += v6.w;
                ax += v7.x; ay += v7.y; az += v7.z; aw += v7.w;
            }
            float4 o; o.x = ax; o.y = ay; o.z = az; o.w = aw;
            *((float4*)&g_Fpart[chunk][b * PIX + t * 4]) = o;
        }
        /* handoff: last block for this image sums the 64 partials -> g_F[b] */
        __threadfence();
        __syncthreads();
        __shared__ unsigned int s_old;
        if (t == 0) s_old = atomicAdd(&g_done_r[b], 1u);
        __syncthreads();
        if (s_old == NCH - 1) {
            if (t < PIX / 4) {
                float sx = 0.f, sy = 0.f, sz = 0.f, sw = 0.f;
#pragma unroll 8
                for (int c = 0; c < NCH; ++c) {
                    float4 v = __ldcg((const float4*)&g_Fpart[c][b * PIX + t * 4]);
                    sx += v.x; sy += v.y; sz += v.z; sw += v.w;
                }
                float4 o; o.x = sx; o.y = sy; o.z = sz; o.w = sw;
                *((float4*)&g_F[b][t * 4]) = o;
            }
            if (t == 0) g_done_r[b] = 0u;   /* reset for next graph replay */
            __threadfence();
        }
        cudaTriggerProgrammaticLaunchCompletion();
        return;
    }
    if (bid < RBLK + IBLK) {
        /* ---- init branch: cumulative bilinear-resize weight table ---- */
        int idx = (bid - RBLK) * 448 + t;
        if (idx < (HW + 1) * HFn) {
            int y = idx / HFn;     /* 0..1333 */
            int p = idx % HFn;     /* 0..41  */
            const float isc = (float)HFn / (float)HW;
            int ilo = 0, ihi = HW - 1;
            if (p > 0) {
                ilo = (int)floorf(((p - 1) + 0.5f) / isc - 0.5f);
                if (ilo < 0) ilo = 0;
            }
            if (p < HFn - 1) {
                ihi = (int)ceilf(((p + 1) + 0.5f) / isc - 0.5f);
                if (ihi > HW - 1) ihi = HW - 1;
            }
            int iend = min(ihi, y - 1);
            float acc = 0.f;
            for (int i = ilo; i <= iend; ++i) {
                float s = (i + 0.5f) * isc - 0.5f;
                float fp0 = floorf(s);
                int p0 = (int)fp0;
                float f = s - fp0;
                float w = 0.f;
                if (p0 < 0)            { if (p == 0)       w = 1.f; }
                else if (p0 >= HFn-1)  { if (p == HFn-1)   w = 1.f; }
                else                   { if (p == p0)      w = 1.f - f;
                                         else if (p == p0+1) w = f; }
                acc += w;
            }
            g_A[y][p] = acc;
        }
        __threadfence();
        cudaTriggerProgrammaticLaunchCompletion();
        return;
    }
    /* ---- softmax-table branch: warp-per-query, hidden under the DRAM stream ---- */
    {
        int warp = t >> 5, lane = t & 31;
        int task = (bid - RBLK - IBLK) * 14 + warp;
        if (task < NB * Qn) {
            int tb = task / Qn;
            int tq = task - tb * Qn;
            const float* lg = logits + ((size_t)(tb * Qn + tq)) * CCn;
            float lm, se, se2;
            row_softmax(lg, lane, lm, se, se2);
            if (lane == 0) {
                float inv = 1.f / se, pmax = inv;
                float lse2 = logf(se2);
                g_lm[tb][tq] = lm;
                g_inv[tb][tq] = inv;
                g_lse2[tb][tq] = lse2;
                float p90 = expf(lg[NCLS - 1] - lm) * inv;
                g_ce90[tb][tq] = -((p90 - pmax) - lse2);
                float obj = lg[NCLS];
                float sg = sigmoid_stable(obj);
                g_bceobj[tb][tq] = -fmaxf(logf(sg), -100.f);
                g_rest[tb][tq] = rest_term(obj);
            }
        }
        __threadfence();
        cudaTriggerProgrammaticLaunchCompletion();
    }
}

/* -- kernel 2 (PDL secondary): box means; last block per image runs loss tail -- */
__global__ void __launch_bounds__(256) k_means(const float* __restrict__ boxes,
                                               const float* __restrict__ logits,
                                               const int*   __restrict__ tgt_labels,
                                               const float* __restrict__ tgt_boxes,
                                               const int*   __restrict__ query_idx,
                                               const int*   __restrict__ tgt_idx,
                                               float* __restrict__ out) {
    int b = blockIdx.y;
    int t = threadIdx.x;
    int warp = t >> 5;
    int lane = t & 31;
    int q = blockIdx.x * 8 + warp;

    /* pre-sync: prefetch this warp's box (cold DRAM) while k_front drains */
    float4 boxv = make_float4(0.f, 0.f, 0.f, 0.f);
    if (q < Qn)
        boxv = *((const float4*)(boxes + ((size_t)(b * Qn + q)) * 4));

    cudaGridDependencySynchronize();

    __shared__ float sF[HFn * FPAD];
    __shared__ float sdB[8][HFn];
    __shared__ int   s_last;

    for (int i = t; i < PIX; i += 256) {
        int p = i / HFn, j = i - p * HFn;
        sF[p * FPAD + j] = g_F[b][i];
    }
    __syncthreads();

    if (q < Qn) {
        float cx = boxv.x, cy = boxv.y, bw = boxv.z, bh = boxv.w;
        float bx1 = (cx - bw * 0.5f) * (float)HW;
        float by1 = (cy - bh * 0.5f) * (float)HW;
        float bx2 = (cx + bw * 0.5f) * (float)HW;
        float by2 = (cy + bh * 0.5f) * (float)HW;
        int x1 = min(max((int)bx1, 0), HW);
        int y1 = min(max((int)by1, 0), HW);
        int x2 = min(max((int)bx2, 0), HW);
        int y2 = min(max((int)by2, 0), HW);
        int cnt = max(y2 - y1, 0) * max(x2 - x1, 0);

        if (cnt <= 0) {
            if (lane == 0) g_means[b][q] = NEGV;
        } else {
            int x2e = max(x2, x1), y2e = max(y2, y1);
            sdB[warp][lane] = g_A[x2e][lane] - g_A[x1][lane];
            if (lane < HFn - 32)
                sdB[warp][32 + lane] = g_A[x2e][32 + lane] - g_A[x1][32 + lane];
            __syncwarp();
            float acc = 0.f;
#pragma unroll
            for (int pp = 0; pp < 2; ++pp) {
                int p = lane + pp * 32;
                if (p < HFn) {
                    float da = g_A[y2e][p] - g_A[y1][p];
                    if (da != 0.f) {
                        const float* Fr = &sF[p * FPAD];
                        const float* dB = sdB[warp];
                        float s0 = 0.f, s1 = 0.f;
#pragma unroll
                        for (int j = 0; j < HFn; j += 2) {
                            s0 += Fr[j]     * dB[j];
                            s1 += Fr[j + 1] * dB[j + 1];
                        }
                        acc += da * (s0 + s1);
                    }
                }
            }
#pragma unroll
            for (int off = 16; off > 0; off >>= 1)
                acc += __shfl_xor_sync(0xFFFFFFFFu, acc, off);
            if (lane == 0)
                g_means[b][q] = acc * (1.f / (float)CFn) / (float)cnt;
        }
    }

    /* ======== handoff: last block per image runs the table-lookup loss tail ======== */
    __threadfence();
    __syncthreads();
    if (t == 0) {
        unsigned int old = atomicAdd(&g_done_m[b], 1u);
        s_last = (old == MBLK - 1) ? 1 : 0;
        if (s_last) g_done_m[b] = 0u;       /* reset for next graph replay */
    }
    __syncthreads();
    if (!s_last) return;

    __shared__ float smean[320];
    __shared__ float s_rest[320];
    __shared__ unsigned char excl[320];
    __shared__ int   stopk[TOPKn];
    __shared__ float vce[Mn], vbce[Mn], vl1[Mn], viou[Mn];
    __shared__ float rest_s[6];

    for (int i = t; i < 320; i += 256) {
        excl[i] = 0;
        if (i < Qn) {
            smean[i] = __ldcg(&g_means[b][i]);
            s_rest[i] = __ldcg(&g_rest[b][i]);
        } else { smean[i] = NEGV; s_rest[i] = 0.f; }
    }
    __syncthreads();

    if (t < Mn) { int qi = query_idx[b * Mn + t]; smean[qi] = NEGV; excl[qi] = 1; }
    __syncthreads();

    /* topk (w0) | matched items (w1, one thread each) | rest sum (w2-7) */
    if (warp == 0) {
        float vals[10];
#pragma unroll
        for (int i = 0; i < 10; ++i) vals[i] = smean[i * 32 + lane];
#pragma unroll
        for (int k = 0; k < TOPKn; ++k) {
            float bv = -3.4e38f; int bi = 0;
#pragma unroll
            for (int i = 0; i < 10; ++i)
                if (vals[i] > bv) { bv = vals[i]; bi = i; }
            int bq = bi * 32 + lane;
#pragma unroll
            for (int off = 16; off > 0; off >>= 1) {
                float ov = __shfl_xor_sync(0xFFFFFFFFu, bv, off);
                int   oq = __shfl_xor_sync(0xFFFFFFFFu, bq, off);
                if (ov > bv || (ov == bv && oq < bq)) { bv = ov; bq = oq; }
            }
            if (lane == 0) stopk[k] = bq;
            if ((bq & 31) == lane) vals[bq >> 5] = -3.4e38f;
        }
    } else if (warp == 1) {
        int m = t - 32;
        if (m < Mn) {
            int qi = query_idx[b * Mn + m];
            int ti = tgt_idx[b * Mn + m];
            int tc = tgt_labels[b * Mn + ti];
            float lm = g_lm[b][qi];
            float inv = g_inv[b][qi];
            float lse2 = g_lse2[b][qi];
            float ptl = logits[((size_t)(b * Qn + qi)) * CCn + tc];
            float pt = expf(ptl - lm) * inv;
            vce[m] = -((pt - inv) - lse2);
            vbce[m] = g_bceobj[b][qi];

            const float* qb = boxes + ((size_t)(b * Qn + qi)) * 4;
            const float* tb = tgt_boxes + (size_t)(b * Mn + ti) * 4;
            float tbx[4];
            const float inv_s = 1.f / (float)HW;
#pragma unroll
            for (int j = 0; j < 4; ++j) tbx[j] = tb[j] * inv_s;
            float s4 = 0.f;
#pragma unroll
            for (int j = 0; j < 4; ++j) { float e = qb[j] - tbx[j]; s4 += e * e; }
            vl1[m] = s4;

            float ax1 = qb[0] - qb[2] * 0.5f, ay1 = qb[1] - qb[3] * 0.5f;
            float ax2 = qb[0] + qb[2] * 0.5f, ay2 = qb[1] + qb[3] * 0.5f;
            float tx1 = tbx[0] - tbx[2] * 0.5f, ty1 = tbx[1] - tbx[3] * 0.5f;
            float tx2 = tbx[0] + tbx[2] * 0.5f, ty2 = tbx[1] + tbx[3] * 0.5f;
            float ix1 = fmaxf(ax1, tx1), iy1 = fmaxf(ay1, ty1);
            float ix2 = fminf(ax2, tx2), iy2 = fminf(ay2, ty2);
            float inter = fmaxf(ix2 - ix1, 0.f) * fmaxf(iy2 - iy1, 0.f);
            float areaA = (ax2 - ax1) * (ay2 - ay1);
            float areaT = (tx2 - tx1) * (ty2 - ty1);
            float iou = inter / (areaA + areaT - inter + 1e-9f);
            viou[m] = 1.f - iou;
        }
    } else {
        int base = t - 64;                 /* 0..191 */
        float rs = 0.f;
        if (base < Qn && !excl[base]) rs += s_rest[base];
        int q2 = base + 192;
        if (q2 < Qn && !excl[q2]) rs += s_rest[q2];
#pragma unroll
        for (int off = 16; off > 0; off >>= 1)
            rs += __shfl_xor_sync(0xFFFFFFFFu, rs, off);
        if (lane == 0) rest_s[warp - 2] = rs;
    }
    __syncthreads();

    /* combine + cross-image finish */
    if (t == 0) {
        float ce = 0.f, bc = 0.f, l1 = 0.f, io = 0.f;
        for (int m = 0; m < Mn; ++m) { ce += vce[m]; bc += vbce[m]; l1 += vl1[m]; io += viou[m]; }
        float cep = 0.f, bct = 0.f;
        for (int k = 0; k < TOPKn; ++k) {
            int qi = stopk[k];
            cep += g_ce90[b][qi];
            bct += g_bceobj[b][qi];
        }
        float rsum = 0.f;
        for (int i = 0; i < 6; ++i) rsum += rest_s[i];
        for (int k = 0; k < TOPKn; ++k) rsum -= s_rest[stopk[k]];
        float bce_rest = rsum / (float)(Qn - Mn - TOPKn);
        float cls = ce / (float)Mn + cep / (float)TOPKn;
        float obj = bc / (float)Mn + bce_rest + bct / (float)TOPKn;
        g_partial[b] = 2.f * cls + 2.f * obj + 2.f * io + 5.f * sqrtf(l1);
        __threadfence();
        unsigned int old = atomicAdd(&g_ctr, 1u);
        if (old == NB - 1) {
            volatile float* gp = g_partial;
            float s = 0.f;
            for (int i = 0; i < NB; ++i) s += gp[i];
            out[0] = s;
            g_ctr = 0u;                     /* reset for next graph replay */
        }
    }
}

extern "C" void kernel_launch(void* const* d_in, const int* in_sizes, int n_in,
                              void* d_out, int out_size) {
    const float* img        = (const float*)d_in[0];
    const float* logits     = (const float*)d_in[1];
    const float* boxes      = (const float*)d_in[2];
    const int*   tgt_labels = (const int*)  d_in[3];
    const float* tgt_boxes  = (const float*)d_in[4];
    const int*   query_idx  = (const int*)  d_in[5];
    const int*   tgt_idx    = (const int*)  d_in[6];
    float* out = (float*)d_out;

    k_front<<<FGRID, 448>>>(img, logits);

    /* PDL secondary: overlaps its launch/ramp with k_front's drain */
    cudaLaunchConfig_t cfg = {};
    cfg.gridDim = dim3(MBLK, NB);
    cfg.blockDim = dim3(256);
    cfg.dynamicSmemBytes = 0;
    cfg.stream = 0;
    cudaLaunchAttribute attrs[1];
    attrs[0].id = cudaLaunchAttributeProgrammaticStreamSerialization;
    attrs[0].val.programmaticStreamSerializationAllowed = 1;
    cfg.attrs = attrs;
    cfg.numAttrs = 1;
    cudaLaunchKernelEx(&cfg, k_means, boxes, logits, tgt_labels, tgt_boxes,
                       query_idx, tgt_idx, out);
}

// round 17
// speedup vs baseline: 1.0463x; 1.0463x over previous
#include <cuda_runtime.h>
#include <math.h>

#define NB 8
#define Qn 300
#define CCn 92
#define CFn 2048
#define HFn 42
#define Mn 20
#define TOPKn 5
#define NCLS 91
#define HW 1333
#define PIX (HFn*HFn)       /* 1764 */
#define NEGV (-1e11f)
#define NCH 64              /* channel chunks, 32 channels each */
#define FPAD 43             /* padded row stride (conflict-free) */
#define MBLK 38             /* means blocks per image */
#define IBLK 16             /* init-table blocks (x range) */
#define TBLK 22             /* softmax-table blocks (14 warps each) */

__device__ float g_Fpart[NCH][NB*PIX];
__device__ float g_F[NB][PIX];
__device__ float g_A[HW+1][HFn];     /* cumulative bilinear weights */
__device__ float g_means[NB][Qn];
/* per-query tables, computed concurrently with the DRAM-bound reduce */
__device__ float g_lm[NB][Qn];
__device__ float g_inv[NB][Qn];
__device__ float g_lse2[NB][Qn];
__device__ float g_ce90[NB][Qn];
__device__ float g_bceobj[NB][Qn];
__device__ float g_rest[NB][Qn];
__device__ float g_partial[NB];
__device__ unsigned int g_done_r[NB];   /* zero-init; self-resetting */
__device__ unsigned int g_done_m[NB];   /* zero-init; self-resetting */
__device__ unsigned int g_ctr;          /* zero-init; self-resetting */

/* ---------------- helpers ---------------- */
__device__ __forceinline__ float sigmoid_stable(float x) {
    if (x >= 0.f) return 1.f / (1.f + expf(-x));
    float e = expf(x);
    return e / (1.f + e);
}

__device__ __forceinline__ float rest_term(float x) {
    float sg = sigmoid_stable(x);
    return -fmaxf(log1pf(-sg), -100.f);
}

/* warp-collective softmax stats over one 91-class row */
__device__ __forceinline__ void row_softmax(const float* __restrict__ lg,
                                            int lane, float& lm, float& se, float& se2) {
    lm = -3.4e38f;
    for (int c = lane; c < NCLS; c += 32) lm = fmaxf(lm, lg[c]);
#pragma unroll
    for (int off = 16; off > 0; off >>= 1)
        lm = fmaxf(lm, __shfl_xor_sync(0xFFFFFFFFu, lm, off));
    se = 0.f;
    for (int c = lane; c < NCLS; c += 32) se += expf(lg[c] - lm);
#pragma unroll
    for (int off = 16; off > 0; off >>= 1)
        se += __shfl_xor_sync(0xFFFFFFFFu, se, off);
    float inv = 1.f / se, pmax = inv;
    se2 = 0.f;
    for (int c = lane; c < NCLS; c += 32)
        se2 += expf(expf(lg[c] - lm) * inv - pmax);
#pragma unroll
    for (int off = 16; off > 0; off >>= 1)
        se2 += __shfl_xor_sync(0xFFFFFFFFu, se2, off);
}

/* -- kernel 1: channel reduce (+fused F sum) | weight-table init | softmax tables -- */
__global__ void __launch_bounds__(448, 3) k_front(const float* __restrict__ img,
                                                  const float* __restrict__ logits) {
    int b = blockIdx.y;
    int t = threadIdx.x;
    if (blockIdx.x < NCH) {
        int chunk = blockIdx.x;            /* 0..63, 32 channels each */
        if (t < PIX / 4) {
            const float4* base = (const float4*)img + ((size_t)b * CFn + (size_t)chunk * 32) * (PIX / 4) + t;
            float ax = 0.f, ay = 0.f, az = 0.f, aw = 0.f;
#pragma unroll
            for (int c = 0; c < 32; c += 8) {
                float4 v0 = base[(size_t)(c + 0) * (PIX / 4)];
                float4 v1 = base[(size_t)(c + 1) * (PIX / 4)];
                float4 v2 = base[(size_t)(c + 2) * (PIX / 4)];
                float4 v3 = base[(size_t)(c + 3) * (PIX / 4)];
                float4 v4 = base[(size_t)(c + 4) * (PIX / 4)];
                float4 v5 = base[(size_t)(c + 5) * (PIX / 4)];
                float4 v6 = base[(size_t)(c + 6) * (PIX / 4)];
                float4 v7 = base[(size_t)(c + 7) * (PIX / 4)];
                ax += v0.x; ay += v0.y; az += v0.z; aw += v0.w;
                ax += v1.x; ay += v1.y; az += v1.z; aw += v1.w;
                ax += v2.x; ay += v2.y; az += v2.z; aw += v2.w;
                ax += v3.x; ay += v3.y; az += v3.z; aw += v3.w;
                ax += v4.x; ay += v4.y; az += v4.z; aw += v4.w;
                ax += v5.x; ay += v5.y; az += v5.z; aw += v5.w;
                ax += v6.x; ay += v6.y; az += v6.z; aw += v6.w;
                ax += v7.x; ay += v7.y; az += v7.z; aw += v7.w;
            }
            float4 o; o.x = ax; o.y = ay; o.z = az; o.w = aw;
            *((float4*)&g_Fpart[chunk][b * PIX + t * 4]) = o;
        }
        /* handoff: last block for this image sums the 64 partials -> g_F[b] */
        __threadfence();
        __syncthreads();
        __shared__ unsigned int s_old;
        if (t == 0) s_old = atomicAdd(&g_done_r[b], 1u);
        __syncthreads();
        if (s_old == NCH - 1) {
            if (t < PIX / 4) {
                float sx = 0.f, sy = 0.f, sz = 0.f, sw = 0.f;
#pragma unroll 8
                for (int c = 0; c < NCH; ++c) {
                    float4 v = __ldcg((const float4*)&g_Fpart[c][b * PIX + t * 4]);
                    sx += v.x; sy += v.y; sz += v.z; sw += v.w;
                }
                float4 o; o.x = sx; o.y = sy; o.z = sz; o.w = sw;
                *((float4*)&g_F[b][t * 4]) = o;
            }
            if (t == 0) g_done_r[b] = 0u;   /* reset for next graph replay */
        }
        return;
    }
    if (blockIdx.x < NCH + IBLK) {
        /* ---- init branch: cumulative bilinear-resize weight table ---- */
        int idx = ((blockIdx.x - NCH) * NB + b) * 448 + t;
        int total = (HW + 1) * HFn;
        if (idx >= total) return;
        int y = idx / HFn;     /* 0..1333 */
        int p = idx % HFn;     /* 0..41  */
        const float isc = (float)HFn / (float)HW;
        int ilo = 0, ihi = HW - 1;
        if (p > 0) {
            ilo = (int)floorf(((p - 1) + 0.5f) / isc - 0.5f);
            if (ilo < 0) ilo = 0;
        }
        if (p < HFn - 1) {
            ihi = (int)ceilf(((p + 1) + 0.5f) / isc - 0.5f);
            if (ihi > HW - 1) ihi = HW - 1;
        }
        int iend = min(ihi, y - 1);
        float acc = 0.f;
        for (int i = ilo; i <= iend; ++i) {
            float s = (i + 0.5f) * isc - 0.5f;
            float fp0 = floorf(s);
            int p0 = (int)fp0;
            float f = s - fp0;
            float w = 0.f;
            if (p0 < 0)            { if (p == 0)       w = 1.f; }
            else if (p0 >= HFn-1)  { if (p == HFn-1)   w = 1.f; }
            else                   { if (p == p0)      w = 1.f - f;
                                     else if (p == p0+1) w = f; }
            acc += w;
        }
        g_A[y][p] = acc;
        return;
    }
    /* ---- softmax-table branch: warp-per-query, hidden under the DRAM stream ---- */
    {
        int warp = t >> 5, lane = t & 31;
        int q = (blockIdx.x - NCH - IBLK) * 14 + warp;
        if (q >= Qn) return;
        const float* lg = logits + ((size_t)(b * Qn + q)) * CCn;
        float lm, se, se2;
        row_softmax(lg, lane, lm, se, se2);
        if (lane == 0) {
            float inv = 1.f / se, pmax = inv;
            float lse2 = logf(se2);
            g_lm[b][q] = lm;
            g_inv[b][q] = inv;
            g_lse2[b][q] = lse2;
            float p90 = expf(lg[NCLS - 1] - lm) * inv;
            g_ce90[b][q] = -((p90 - pmax) - lse2);
            float obj = lg[NCLS];
            float sg = sigmoid_stable(obj);
            g_bceobj[b][q] = -fmaxf(logf(sg), -100.f);
            g_rest[b][q] = rest_term(obj);
        }
    }
}

/* -- kernel 2: box means (all blocks); last block per image runs table-lookup loss -- */
__global__ void __launch_bounds__(256) k_means(const float* __restrict__ boxes,
                                               const float* __restrict__ logits,
                                               const int*   __restrict__ tgt_labels,
                                               const float* __restrict__ tgt_boxes,
                                               const int*   __restrict__ query_idx,
                                               const int*   __restrict__ tgt_idx,
                                               float* __restrict__ out) {
    int b = blockIdx.y;
    int t = threadIdx.x;
    int warp = t >> 5;
    int lane = t & 31;
    int q = blockIdx.x * 8 + warp;

    __shared__ float sF[HFn * FPAD];
    __shared__ float sdB[8][HFn];
    __shared__ int   s_last;

    for (int i = t; i < PIX; i += 256) {
        int p = i / HFn, j = i - p * HFn;
        sF[p * FPAD + j] = g_F[b][i];
    }
    __syncthreads();

    if (q < Qn) {
        const float* pb = boxes + ((size_t)(b * Qn + q)) * 4;
        float cx = pb[0], cy = pb[1], bw = pb[2], bh = pb[3];
        float bx1 = (cx - bw * 0.5f) * (float)HW;
        float by1 = (cy - bh * 0.5f) * (float)HW;
        float bx2 = (cx + bw * 0.5f) * (float)HW;
        float by2 = (cy + bh * 0.5f) * (float)HW;
        int x1 = min(max((int)bx1, 0), HW);
        int y1 = min(max((int)by1, 0), HW);
        int x2 = min(max((int)bx2, 0), HW);
        int y2 = min(max((int)by2, 0), HW);
        int cnt = max(y2 - y1, 0) * max(x2 - x1, 0);

        if (cnt <= 0) {
            if (lane == 0) g_means[b][q] = NEGV;
        } else {
            int x2e = max(x2, x1), y2e = max(y2, y1);
            sdB[warp][lane] = g_A[x2e][lane] - g_A[x1][lane];
            if (lane < HFn - 32)
                sdB[warp][32 + lane] = g_A[x2e][32 + lane] - g_A[x1][32 + lane];
            __syncwarp();
            float acc = 0.f;
#pragma unroll
            for (int pp = 0; pp < 2; ++pp) {
                int p = lane + pp * 32;
                if (p < HFn) {
                    float da = g_A[y2e][p] - g_A[y1][p];
                    if (da != 0.f) {
                        const float* Fr = &sF[p * FPAD];
                        const float* dB = sdB[warp];
                        float s0 = 0.f, s1 = 0.f;
#pragma unroll
                        for (int j = 0; j < HFn; j += 2) {
                            s0 += Fr[j]     * dB[j];
                            s1 += Fr[j + 1] * dB[j + 1];
                        }
                        acc += da * (s0 + s1);
                    }
                }
            }
#pragma unroll
            for (int off = 16; off > 0; off >>= 1)
                acc += __shfl_xor_sync(0xFFFFFFFFu, acc, off);
            if (lane == 0)
                g_means[b][q] = acc * (1.f / (float)CFn) / (float)cnt;
        }
    }

    /* ======== handoff: last block per image runs the table-lookup loss tail ======== */
    __threadfence();
    __syncthreads();
    if (t == 0) {
        unsigned int old = atomicAdd(&g_done_m[b], 1u);
        s_last = (old == MBLK - 1) ? 1 : 0;
        if (s_last) g_done_m[b] = 0u;       /* reset for next graph replay */
    }
    __syncthreads();
    if (!s_last) return;

    __shared__ float smean[320];
    __shared__ float s_rest[320];
    __shared__ float s_ce90[Qn];
    __shared__ float s_bce[Qn];
    __shared__ float s_lm[Qn];
    __shared__ float s_inv[Qn];
    __shared__ float s_lse2[Qn];
    __shared__ unsigned char excl[320];
    __shared__ int   stopk[TOPKn];
    __shared__ float vce[Mn], vbce[Mn], vl1[Mn], viou[Mn];
    __shared__ float rest_s[6];

    /* parallel prefetch of ALL per-query tables into smem (one L2 round) */
    for (int i = t; i < 320; i += 256) {
        excl[i] = 0;
        if (i < Qn) {
            smean[i]  = __ldcg(&g_means[b][i]);
            s_rest[i] = __ldcg(&g_rest[b][i]);
            s_ce90[i] = __ldcg(&g_ce90[b][i]);
            s_bce[i]  = __ldcg(&g_bceobj[b][i]);
            s_lm[i]   = __ldcg(&g_lm[b][i]);
            s_inv[i]  = __ldcg(&g_inv[b][i]);
            s_lse2[i] = __ldcg(&g_lse2[b][i]);
        } else { smean[i] = NEGV; s_rest[i] = 0.f; }
    }
    __syncthreads();

    if (t < Mn) { int qi = query_idx[b * Mn + t]; smean[qi] = NEGV; excl[qi] = 1; }
    __syncthreads();

    /* topk (w0) | matched items (w1, one thread each) | rest sum (w2-7) */
    if (warp == 0) {
        float vals[10];
#pragma unroll
        for (int i = 0; i < 10; ++i) vals[i] = smean[i * 32 + lane];
#pragma unroll
        for (int k = 0; k < TOPKn; ++k) {
            float bv = -3.4e38f; int bi = 0;
#pragma unroll
            for (int i = 0; i < 10; ++i)
                if (vals[i] > bv) { bv = vals[i]; bi = i; }
            int bq = bi * 32 + lane;
#pragma unroll
            for (int off = 16; off > 0; off >>= 1) {
                float ov = __shfl_xor_sync(0xFFFFFFFFu, bv, off);
                int   oq = __shfl_xor_sync(0xFFFFFFFFu, bq, off);
                if (ov > bv || (ov == bv && oq < bq)) { bv = ov; bq = oq; }
            }
            if (lane == 0) stopk[k] = bq;
            if ((bq & 31) == lane) vals[bq >> 5] = -3.4e38f;
        }
    } else if (warp == 1) {
        int m = t - 32;
        if (m < Mn) {
            int qi = query_idx[b * Mn + m];
            int ti = tgt_idx[b * Mn + m];
            int tc = tgt_labels[b * Mn + ti];
            float lm = s_lm[qi];
            float inv = s_inv[qi];
            float lse2 = s_lse2[qi];
            float ptl = logits[((size_t)(b * Qn + qi)) * CCn + tc];
            float pt = expf(ptl - lm) * inv;
            vce[m] = -((pt - inv) - lse2);
            vbce[m] = s_bce[qi];

            const float* qb = boxes + ((size_t)(b * Qn + qi)) * 4;
            const float* tb = tgt_boxes + (size_t)(b * Mn + ti) * 4;
            float tbx[4];
            const float inv_s = 1.f / (float)HW;
#pragma unroll
            for (int j = 0; j < 4; ++j) tbx[j] = tb[j] * inv_s;
            float s4 = 0.f;
#pragma unroll
            for (int j = 0; j < 4; ++j) { float e = qb[j] - tbx[j]; s4 += e * e; }
            vl1[m] = s4;

            float ax1 = qb[0] - qb[2] * 0.5f, ay1 = qb[1] - qb[3] * 0.5f;
            float ax2 = qb[0] + qb[2] * 0.5f, ay2 = qb[1] + qb[3] * 0.5f;
            float tx1 = tbx[0] - tbx[2] * 0.5f, ty1 = tbx[1] - tbx[3] * 0.5f;
            float tx2 = tbx[0] + tbx[2] * 0.5f, ty2 = tbx[1] + tbx[3] * 0.5f;
            float ix1 = fmaxf(ax1, tx1), iy1 = fmaxf(ay1, ty1);
            float ix2 = fminf(ax2, tx2), iy2 = fminf(ay2, ty2);
            float inter = fmaxf(ix2 - ix1, 0.f) * fmaxf(iy2 - iy1, 0.f);
            float areaA = (ax2 - ax1) * (ay2 - ay1);
            float areaT = (tx2 - tx1) * (ty2 - ty1);
            float iou = inter / (areaA + areaT - inter + 1e-9f);
            viou[m] = 1.f - iou;
        }
    } else {
        int base = t - 64;                 /* 0..191 */
        float rs = 0.f;
        if (base < Qn && !excl[base]) rs += s_rest[base];
        int q2 = base + 192;
        if (q2 < Qn && !excl[q2]) rs += s_rest[q2];
#pragma unroll
        for (int off = 16; off > 0; off >>= 1)
            rs += __shfl_xor_sync(0xFFFFFFFFu, rs, off);
        if (lane == 0) rest_s[warp - 2] = rs;
    }
    __syncthreads();

    /* combine (all-smem) + cross-image finish (R14-proven volatile form) */
    if (t == 0) {
        float ce = 0.f, bc = 0.f, l1 = 0.f, io = 0.f;
        for (int m = 0; m < Mn; ++m) { ce += vce[m]; bc += vbce[m]; l1 += vl1[m]; io += viou[m]; }
        float cep = 0.f, bct = 0.f;
        for (int k = 0; k < TOPKn; ++k) {
            int qi = stopk[k];
            cep += s_ce90[qi];
            bct += s_bce[qi];
        }
        float rsum = 0.f;
        for (int i = 0; i < 6; ++i) rsum += rest_s[i];
        for (int k = 0; k < TOPKn; ++k) rsum -= s_rest[stopk[k]];
        float bce_rest = rsum / (float)(Qn - Mn - TOPKn);
        float cls = ce / (float)Mn + cep / (float)TOPKn;
        float obj = bc / (float)Mn + bce_rest + bct / (float)TOPKn;
        g_partial[b] = 2.f * cls + 2.f * obj + 2.f * io + 5.f * sqrtf(l1);
        __threadfence();
        unsigned int old = atomicAdd(&g_ctr, 1u);
        if (old == NB - 1) {
            volatile float* gp = g_partial;
            float s = 0.f;
            for (int i = 0; i < NB; ++i) s += gp[i];
            out[0] = s;
            g_ctr = 0u;                     /* reset for next graph replay */
        }
    }
}

extern "C" void kernel_launch(void* const* d_in, const int* in_sizes, int n_in,
                              void* d_out, int out_size) {
    const float* img        = (const float*)d_in[0];
    const float* logits     = (const float*)d_in[1];
    const float* boxes      = (const float*)d_in[2];
    const int*   tgt_labels = (const int*)  d_in[3];
    const float* tgt_boxes  = (const float*)d_in[4];
    const int*   query_idx  = (const int*)  d_in[5];
    const int*   tgt_idx    = (const int*)  d_in[6];
    float* out = (float*)d_out;

    k_front<<<dim3(NCH + IBLK + TBLK, NB), 448>>>(img, logits);
    k_means<<<dim3(MBLK, NB), 256>>>(boxes, logits, tgt_labels, tgt_boxes,
                                     query_idx, tgt_idx, out);
}